// round 13
// baseline (speedup 1.0000x reference)
#include <cuda_runtime.h>
#include <cuda_fp16.h>
#include <cstdint>
#include <cstring>

// Problem constants (fixed by the dataset)
#define LL 256
#define ROWS_PER_WARP 8
#define WARPS_PER_BLOCK 4
#define THREADS_PER_BLOCK (WARPS_PER_BLOCK * 32)
#define ROWS_PER_BLOCK (WARPS_PER_BLOCK * ROWS_PER_WARP)   // 32

typedef unsigned int u32;
typedef unsigned long long ull;

// ---------- f32x2 packed helpers ----------
__device__ __forceinline__ ull pack2(float a, float b) {
    ull r;
    asm("mov.b64 %0, {%1, %2};" : "=l"(r)
        : "r"(__float_as_uint(a)), "r"(__float_as_uint(b)));
    return r;
}
__device__ __forceinline__ void unpack2(ull v, float& a, float& b) {
    u32 x, y;
    asm("mov.b64 {%0, %1}, %2;" : "=r"(x), "=r"(y) : "l"(v));
    a = __uint_as_float(x);
    b = __uint_as_float(y);
}
__device__ __forceinline__ ull fma2(ull a, ull b, ull c) {
    ull d;
    asm("fma.rn.f32x2 %0, %1, %2, %3;" : "=l"(d) : "l"(a), "l"(b), "l"(c));
    return d;
}
__device__ __forceinline__ ull add2(ull a, ull b) {
    ull d;
    asm("add.rn.f32x2 %0, %1, %2;" : "=l"(d) : "l"(a), "l"(b));
    return d;
}

// ---------- half2 helpers ----------
__device__ __forceinline__ u32 h2_bits(__half2 h) {
    u32 v;
    memcpy(&v, &h, 4);
    return v;
}
__device__ __forceinline__ __half2 bits_h2(u32 v) {
    __half2 h;
    memcpy(&h, &v, 4);
    return h;
}
// packed HW tanh: one MUFU op for two fp16 values (~1e-3 abs incl. fp16 rnd)
__device__ __forceinline__ u32 tanh2(u32 x) {
    u32 y;
    asm("tanh.approx.f16x2 %0, %1;" : "=r"(y) : "r"(x));
    return y;
}
// cvt.rn.f16x2.f32 d, a, b -> d = {hi = a, lo = b}
__device__ __forceinline__ u32 f16x2_of(float hi, float lo) {
    u32 r;
    asm("cvt.rn.f16x2.f32 %0, %1, %2;" : "=r"(r) : "f"(hi), "f"(lo));
    return r;
}

// mma.sync m16n8k16 row.col f32.f16.f16.f32
__device__ __forceinline__ void mma16816(
    float& d0, float& d1, float& d2, float& d3,
    u32 a0, u32 a1, u32 a2, u32 a3,
    u32 b0, u32 b1,
    float c0, float c1, float c2, float c3)
{
    asm("mma.sync.aligned.m16n8k16.row.col.f32.f16.f16.f32 "
        "{%0,%1,%2,%3}, {%4,%5,%6,%7}, {%8,%9}, {%10,%11,%12,%13};"
        : "=f"(d0), "=f"(d1), "=f"(d2), "=f"(d3)
        : "r"(a0), "r"(a1), "r"(a2), "r"(a3),
          "r"(b0), "r"(b1),
          "f"(c0), "f"(c1), "f"(c2), "f"(c3));
}

// Extended weight matrix: rows 0..31 = Wh, 32/33 = Wi[0]/Wi[1], 34 = bh,
// 35..47 = 0. Columns: 0-31 i, 32-63 f, 64-95 g, 96-127 o.
// 0.5 prescale on i,f,o (sigmoid(x) = 0.5*tanh(0.5x)+0.5).
__device__ __forceinline__ float wval(int k, int col,
                                      const float* __restrict__ Wh,
                                      const float* __restrict__ Wi,
                                      const float* __restrict__ bh) {
    float v = 0.f;
    if (k < 32) v = Wh[k * 128 + col];
    else if (k == 32) v = Wi[col];
    else if (k == 33) v = Wi[128 + col];
    else if (k == 34) v = bh[col];
    float s = (col >= 64 && col < 96) ? 1.f : 0.5f;
    return v * s;
}

// Each WARP owns 8 batch rows (m16 rows 8-15 pinned to zero; their D slots
// never read). 4 warps/block, 1 block/SM -> one warp per SMSP (private
// scheduler + MUFU). Recurrence lane-local: D fragment layout == next A
// fragment layout. NEW (R13): full half2 activation tail — packed
// tanh.approx.f16x2 halves MUFU issues (40 -> 20 per step), HFMA2/HMUL2
// sigmoid/c/h, and h lands directly in f16x2 A-fragment form (no cvt).
__global__ void __launch_bounds__(THREADS_PER_BLOCK)
lstm_kernel(const int* __restrict__ x,       // [B, L] spins in {0,1}
            const float* __restrict__ Wi,    // [2, 128]
            const float* __restrict__ Wh,    // [32, 128]
            const float* __restrict__ bh,    // [128]
            const float* __restrict__ Wo,    // [32, 2]
            const float* __restrict__ bo,    // [2]
            float* __restrict__ out)         // [B]
{
    __shared__ unsigned char s_x[ROWS_PER_BLOCK * LL];

    const int tid = threadIdx.x;
    const int lane = tid & 31;
    const int warp = tid >> 5;
    const int g = lane >> 2;      // my valid row is g (row g+8 unused)
    const int t = lane & 3;
    const int base_b = blockIdx.x * ROWS_PER_BLOCK + warp * ROWS_PER_WARP;

    // stage the block's spins (coalesced LDG)
    {
        const int blk_b = blockIdx.x * ROWS_PER_BLOCK;
        for (int idx = tid; idx < ROWS_PER_BLOCK * LL; idx += THREADS_PER_BLOCK)
            s_x[idx] = (unsigned char)x[blk_b * LL + idx];
    }
    __syncthreads();
    const unsigned char* xw = s_x + (warp * ROWS_PER_WARP) * LL;  // my 8 rows

    // ---- B fragments (fp16, register-resident, one-time build) ----
    u32 bf[16][3][2];
#pragma unroll
    for (int nt = 0; nt < 16; nt++) {
        const int col = nt * 8 + g;
#pragma unroll
        for (int kt = 0; kt < 3; kt++) {
            const int k0 = kt * 16 + 2 * t;
            bf[nt][kt][0] = f16x2_of(wval(k0 + 1, col, Wh, Wi, bh),
                                     wval(k0,     col, Wh, Wi, bh));
            bf[nt][kt][1] = f16x2_of(wval(k0 + 9, col, Wh, Wi, bh),
                                     wval(k0 + 8, col, Wh, Wi, bh));
        }
    }

    // output-head weights for my 8 units (u = 8m+2t, 8m+2t+1)
    ull wo[8];
#pragma unroll
    for (int m = 0; m < 4; m++) {
        const int u = 8 * m + 2 * t;
        wo[2 * m]     = pack2(Wo[2 * u],     Wo[2 * u + 1]);
        wo[2 * m + 1] = pack2(Wo[2 * u + 2], Wo[2 * u + 3]);
    }
    const float bo0 = bo[0];
    const float bo1 = bo[1];

    // state: c in half2, one pair (u0,u1) per m-tile, row g only
    __half2 cst[4];
#pragma unroll
    for (int i = 0; i < 4; i++) cst[i] = __half2half2(__float2half(0.f));
    const __half2 h05 = __half2half2(__float2half(0.5f));

    u32 A0[4] = {0, 0, 0, 0};
    u32 A1[4] = {0, 0, 0, 0};
    int sel_g = 2;                 // 2 = zero input row (t=0)
    float logp = 0.f;
    const u32 eaC = f16x2_of(0.f, 1.f);   // t==1 ext-A: k34=1 (bh), k35=0
    const float zf = 0.f;

#pragma unroll 1
    for (int step = 0; step < LL; step++) {
        // ---- ext A fragment (k=32..47): onehot(sel) k32/33, 1 at k34 ----
        float lo0 = (t == 0) ? ((sel_g == 0) ? 1.f : 0.f) : 0.f;
        float hi0 = (t == 0) ? ((sel_g == 1) ? 1.f : 0.f) : 0.f;
        u32 ea0 = f16x2_of(hi0, lo0);
        ea0 = (t == 1) ? eaC : ea0;

        u32 nA0[4], nA1[4];
        nA0[1] = 0u; nA0[3] = 0u; nA1[1] = 0u; nA1[3] = 0u;  // rows 8-15 = 0
        ull accg = 0ull;

#pragma unroll
        for (int m = 0; m < 4; m++) {
            float ci0, ci1, ci2, ci3;
            float cf0, cf1, cf2, cf3;
            float cg0, cg1, cg2, cg3;
            float co0, co1, co2, co3;

            mma16816(ci0,ci1,ci2,ci3, A0[0],A0[1],A0[2],A0[3], bf[m][0][0],bf[m][0][1], zf,zf,zf,zf);
            mma16816(ci0,ci1,ci2,ci3, A1[0],A1[1],A1[2],A1[3], bf[m][1][0],bf[m][1][1], ci0,ci1,ci2,ci3);
            mma16816(ci0,ci1,ci2,ci3, ea0,0u,0u,0u,            bf[m][2][0],bf[m][2][1], ci0,ci1,ci2,ci3);

            mma16816(cf0,cf1,cf2,cf3, A0[0],A0[1],A0[2],A0[3], bf[m+4][0][0],bf[m+4][0][1], zf,zf,zf,zf);
            mma16816(cf0,cf1,cf2,cf3, A1[0],A1[1],A1[2],A1[3], bf[m+4][1][0],bf[m+4][1][1], cf0,cf1,cf2,cf3);
            mma16816(cf0,cf1,cf2,cf3, ea0,0u,0u,0u,            bf[m+4][2][0],bf[m+4][2][1], cf0,cf1,cf2,cf3);

            mma16816(cg0,cg1,cg2,cg3, A0[0],A0[1],A0[2],A0[3], bf[m+8][0][0],bf[m+8][0][1], zf,zf,zf,zf);
            mma16816(cg0,cg1,cg2,cg3, A1[0],A1[1],A1[2],A1[3], bf[m+8][1][0],bf[m+8][1][1], cg0,cg1,cg2,cg3);
            mma16816(cg0,cg1,cg2,cg3, ea0,0u,0u,0u,            bf[m+8][2][0],bf[m+8][2][1], cg0,cg1,cg2,cg3);

            mma16816(co0,co1,co2,co3, A0[0],A0[1],A0[2],A0[3], bf[m+12][0][0],bf[m+12][0][1], zf,zf,zf,zf);
            mma16816(co0,co1,co2,co3, A1[0],A1[1],A1[2],A1[3], bf[m+12][1][0],bf[m+12][1][1], co0,co1,co2,co3);
            mma16816(co0,co1,co2,co3, ea0,0u,0u,0u,            bf[m+12][2][0],bf[m+12][2][1], co0,co1,co2,co3);

            (void)ci2; (void)ci3; (void)cf2; (void)cf3;
            (void)cg2; (void)cg3; (void)co2; (void)co3;

            // ---- half2 activation tail: units (u0,u1) of row g ----
            // pack gate pairs (already 0.5-prescaled for i,f,o via B)
            u32 ti = tanh2(f16x2_of(ci1, ci0));
            u32 tf = tanh2(f16x2_of(cf1, cf0));
            u32 tg = tanh2(f16x2_of(cg1, cg0));
            u32 to = tanh2(f16x2_of(co1, co0));

            __half2 si = __hfma2(bits_h2(ti), h05, h05);   // sigmoid(i)
            __half2 sf = __hfma2(bits_h2(tf), h05, h05);   // sigmoid(f)
            __half2 so = __hfma2(bits_h2(to), h05, h05);   // sigmoid(o)

            __half2 cn = __hfma2(sf, cst[m], __hmul2(si, bits_h2(tg)));
            cst[m] = cn;
            __half2 h2 = __hmul2(so, bits_h2(tanh2(h2_bits(cn))));

            // h2 = (lo=h@u0, hi=h@u1): exactly the next-step A fragment
            const u32 pg = h2_bits(h2);
            if (m == 0)      nA0[0] = pg;
            else if (m == 1) nA0[2] = pg;
            else if (m == 2) nA1[0] = pg;
            else             nA1[2] = pg;

            // output-head partial dots in fp32
            float h0 = __low2float(h2);
            float h1 = __high2float(h2);
            accg = fma2(pack2(h0, h0), wo[2 * m],     accg);
            accg = fma2(pack2(h1, h1), wo[2 * m + 1], accg);
        }

        // ---- head: reduce over the quad (lanes sharing g) ----
        accg = add2(accg, __shfl_xor_sync(0xffffffffu, accg, 1));
        accg = add2(accg, __shfl_xor_sync(0xffffffffu, accg, 2));

        float p0, p1;
        unpack2(accg, p0, p1);
        p0 += bo0;
        p1 += bo1;

        const int cur = (int)xw[g * LL + step];

        // elu + 2-class gathered log-softmax
        float e0 = (p0 > 0.f) ? p0 : (__expf(p0) - 1.f);
        float e1 = (p1 > 0.f) ? p1 : (__expf(p1) - 1.f);
        float dg = cur ? (e0 - e1) : (e1 - e0);
        float lpg = __logf(1.f + __expf(dg));
        logp -= (t == 0) ? lpg : 0.f;

        sel_g = cur;
#pragma unroll
        for (int i = 0; i < 4; i++) { A0[i] = nA0[i]; A1[i] = nA1[i]; }
    }

    if (t == 0)
        out[base_b + g] = 0.5f * logp;
}

extern "C" void kernel_launch(void* const* d_in, const int* in_sizes, int n_in,
                              void* d_out, int out_size) {
    const int* x = (const int*)d_in[0];
    const float* Wi = (const float*)d_in[1];
    const float* Wh = (const float*)d_in[2];
    const float* bh = (const float*)d_in[3];
    const float* Wo = (const float*)d_in[4];
    const float* bo = (const float*)d_in[5];
    float* out = (float*)d_out;

    const int batch = in_sizes[0] / LL;              // 4096
    const int blocks = batch / ROWS_PER_BLOCK;       // 128 blocks x 4 warps

    lstm_kernel<<<blocks, THREADS_PER_BLOCK>>>(x, Wi, Wh, bh, Wo, bo, out);
}

// round 15
// speedup vs baseline: 1.4302x; 1.4302x over previous
#include <cuda_runtime.h>
#include <cuda_fp16.h>
#include <cstdint>
#include <cstring>

// Problem constants (fixed by the dataset)
#define LL 256
#define ROWS_PER_WARP 8
#define WARPS_PER_BLOCK 4
#define THREADS_PER_BLOCK (WARPS_PER_BLOCK * 32)
#define ROWS_PER_BLOCK (WARPS_PER_BLOCK * ROWS_PER_WARP)   // 32

typedef unsigned int u32;
typedef unsigned long long ull;

// ---------- f32x2 packed helpers ----------
__device__ __forceinline__ ull pack2(float a, float b) {
    ull r;
    asm("mov.b64 %0, {%1, %2};" : "=l"(r)
        : "r"(__float_as_uint(a)), "r"(__float_as_uint(b)));
    return r;
}
__device__ __forceinline__ void unpack2(ull v, float& a, float& b) {
    u32 x, y;
    asm("mov.b64 {%0, %1}, %2;" : "=r"(x), "=r"(y) : "l"(v));
    a = __uint_as_float(x);
    b = __uint_as_float(y);
}
__device__ __forceinline__ ull fma2(ull a, ull b, ull c) {
    ull d;
    asm("fma.rn.f32x2 %0, %1, %2, %3;" : "=l"(d) : "l"(a), "l"(b), "l"(c));
    return d;
}
__device__ __forceinline__ ull add2(ull a, ull b) {
    ull d;
    asm("add.rn.f32x2 %0, %1, %2;" : "=l"(d) : "l"(a), "l"(b));
    return d;
}

// ---------- half2 helpers ----------
__device__ __forceinline__ u32 h2_bits(__half2 h) {
    u32 v;
    memcpy(&v, &h, 4);
    return v;
}
__device__ __forceinline__ __half2 bits_h2(u32 v) {
    __half2 h;
    memcpy(&h, &v, 4);
    return h;
}
// packed HW tanh: one MUFU op for two fp16 values
__device__ __forceinline__ u32 tanh2(u32 x) {
    u32 y;
    asm("tanh.approx.f16x2 %0, %1;" : "=r"(y) : "r"(x));
    return y;
}
// cvt.rn.f16x2.f32 d, a, b -> d = {hi = a, lo = b}
__device__ __forceinline__ u32 f16x2_of(float hi, float lo) {
    u32 r;
    asm("cvt.rn.f16x2.f32 %0, %1, %2;" : "=r"(r) : "f"(hi), "f"(lo));
    return r;
}

// mma.sync m16n8k16 row.col FP16 ACCUMULATE (full-rate HMMA).
// D/C fragments: {d0, d1}, d0 = packed (row g: col 2t, 2t+1), d1 = row g+8.
__device__ __forceinline__ void mma_f16(
    u32& d0, u32& d1,
    u32 a0, u32 a1, u32 a2, u32 a3,
    u32 b0, u32 b1,
    u32 c0, u32 c1)
{
    asm("mma.sync.aligned.m16n8k16.row.col.f16.f16.f16.f16 "
        "{%0,%1}, {%2,%3,%4,%5}, {%6,%7}, {%8,%9};"
        : "=r"(d0), "=r"(d1)
        : "r"(a0), "r"(a1), "r"(a2), "r"(a3),
          "r"(b0), "r"(b1), "r"(c0), "r"(c1));
}

// gate-column scale: 0.5 on i,f,o (sigmoid(x)=0.5*tanh(0.5x)+0.5), 1.0 on g
__device__ __forceinline__ float gscale(int col) {
    return (col >= 64 && col < 96) ? 1.f : 0.5f;
}

// LSTM activation tail for one packed unit-pair (u0,u1) of one row.
// Inputs: prescaled gate pairs (f16x2). Updates c, returns h pair (f16x2
// bits) — which IS the next-step A-fragment register.
__device__ __forceinline__ u32 lstm_tail(u32 gi, u32 gf, u32 gg, u32 go,
                                         __half2& c, __half2 h05) {
    __half2 si = __hfma2(bits_h2(tanh2(gi)), h05, h05);
    __half2 sf = __hfma2(bits_h2(tanh2(gf)), h05, h05);
    __half2 so = __hfma2(bits_h2(tanh2(go)), h05, h05);
    __half2 tg = bits_h2(tanh2(gg));
    c = __hfma2(sf, c, __hmul2(si, tg));
    return h2_bits(__hmul2(so, bits_h2(tanh2(h2_bits(c)))));
}

// Deferred output head: quad-reduce staged (h*wo0, h*wo1), elu + 2-class
// gathered log-softmax (fp32).
__device__ __forceinline__ float head_update(ull pp, int cur,
                                             float bo0, float bo1,
                                             float logp) {
    pp = add2(pp, __shfl_xor_sync(0xffffffffu, pp, 1));
    pp = add2(pp, __shfl_xor_sync(0xffffffffu, pp, 2));
    float p0, p1;
    unpack2(pp, p0, p1);
    p0 += bo0;
    p1 += bo1;
    float e0 = (p0 > 0.f) ? p0 : (__expf(p0) - 1.f);
    float e1 = (p1 > 0.f) ? p1 : (__expf(p1) - 1.f);
    float d = cur ? (e0 - e1) : (e1 - e0);   // e_other - e_sel
    return logp - __logf(1.f + __expf(d));
}

// Each WARP owns 8 batch rows (m16 rows 8-15 pinned to zero). 4 warps/block,
// 1 block/SM -> one warp per SMSP. Per step: 32 FULL-RATE fp16-acc HMMAs
// (2 dependent per gate-tile; the one-hot/bias init rides as the C operand,
// selected per-step from 2 preloaded f16x2 registers per tile). Step 0 is
// peeled (gates = bh only, no MMA). fp16 D fragment d0 = packed unit pair ->
// tanh.approx.f16x2 directly; tail output = next A fragment. Head deferred
// one step (fp32).
__global__ void __launch_bounds__(THREADS_PER_BLOCK)
lstm_kernel(const int* __restrict__ x,       // [B, L] spins in {0,1}
            const float* __restrict__ Wi,    // [2, 128]
            const float* __restrict__ Wh,    // [32, 128]
            const float* __restrict__ bh,    // [128]
            const float* __restrict__ Wo,    // [32, 2]
            const float* __restrict__ bo,    // [2]
            float* __restrict__ out)         // [B]
{
    __shared__ unsigned char s_x[ROWS_PER_BLOCK * LL];

    const int tid = threadIdx.x;
    const int lane = tid & 31;
    const int warp = tid >> 5;
    const int g = lane >> 2;      // my valid row is g (row g+8 unused)
    const int t = lane & 3;
    const int base_b = blockIdx.x * ROWS_PER_BLOCK + warp * ROWS_PER_WARP;

    // stage the block's spins (coalesced LDG)
    {
        const int blk_b = blockIdx.x * ROWS_PER_BLOCK;
        for (int idx = tid; idx < ROWS_PER_BLOCK * LL; idx += THREADS_PER_BLOCK)
            s_x[idx] = (unsigned char)x[blk_b * LL + idx];
    }
    __syncthreads();
    const unsigned char* xw = s_x + (warp * ROWS_PER_WARP) * LL;  // my 8 rows

    // ---- B fragments: Wh only, 2 k-tiles (fp16, prescaled) ----
    u32 bf[16][2][2];
#pragma unroll
    for (int nt = 0; nt < 16; nt++) {
        const int col = nt * 8 + g;
        const float s = gscale(col);
#pragma unroll
        for (int kt = 0; kt < 2; kt++) {
            const int k0 = kt * 16 + 2 * t;
            bf[nt][kt][0] = f16x2_of(s * Wh[(k0 + 1) * 128 + col],
                                     s * Wh[k0 * 128 + col]);
            bf[nt][kt][1] = f16x2_of(s * Wh[(k0 + 9) * 128 + col],
                                     s * Wh[(k0 + 8) * 128 + col]);
        }
    }

    // ---- init C fragments: (Wi[sel]+bh)*scale, packed pairs, 2 variants ----
    u32 ini0[16], ini1[16];
#pragma unroll
    for (int nt = 0; nt < 16; nt++) {
        const int c0 = nt * 8 + 2 * t;       // my packed cols for this tile
        const int c1 = c0 + 1;
        const float s0 = gscale(c0), s1 = gscale(c1);
        ini0[nt] = f16x2_of(s1 * (Wi[c1] + bh[c1]), s0 * (Wi[c0] + bh[c0]));
        ini1[nt] = f16x2_of(s1 * (Wi[128 + c1] + bh[c1]),
                            s0 * (Wi[128 + c0] + bh[c0]));
    }

    // output-head weights for my 8 units (u = 8m+2t, 8m+2t+1)
    ull wo[8];
#pragma unroll
    for (int m = 0; m < 4; m++) {
        const int u = 8 * m + 2 * t;
        wo[2 * m]     = pack2(Wo[2 * u],     Wo[2 * u + 1]);
        wo[2 * m + 1] = pack2(Wo[2 * u + 2], Wo[2 * u + 3]);
    }
    const float bo0 = bo[0];
    const float bo1 = bo[1];
    const __half2 h05 = __half2half2(__float2half(0.5f));

    __half2 cst[4];
    u32 A0[4] = {0, 0, 0, 0};     // odd slots (rows 8-15) stay 0 forever
    u32 A1[4] = {0, 0, 0, 0};
    float logp = 0.f;
    ull pend;
    int cur_pend;
    int sel_g;

    // ---- step 0 peeled: h=0 -> gates = bh*scale (no MMA) ----
    {
        ull accg = 0ull;
#pragma unroll
        for (int m = 0; m < 4; m++) {
            const int c0 = m * 8 + 2 * t;
            u32 gi = f16x2_of(0.5f * bh[c0 + 1],      0.5f * bh[c0]);
            u32 gf = f16x2_of(0.5f * bh[32 + c0 + 1], 0.5f * bh[32 + c0]);
            u32 gg = f16x2_of(bh[64 + c0 + 1],        bh[64 + c0]);
            u32 go = f16x2_of(0.5f * bh[96 + c0 + 1], 0.5f * bh[96 + c0]);
            cst[m] = __half2half2(__float2half(0.f));
            u32 pg = lstm_tail(gi, gf, gg, go, cst[m], h05);
            if (m == 0)      A0[0] = pg;
            else if (m == 1) A0[2] = pg;
            else if (m == 2) A1[0] = pg;
            else             A1[2] = pg;
            __half2 h2 = bits_h2(pg);
            float h0 = __low2float(h2), h1 = __high2float(h2);
            accg = fma2(pack2(h0, h0), wo[2 * m],     accg);
            accg = fma2(pack2(h1, h1), wo[2 * m + 1], accg);
        }
        pend = accg;
        cur_pend = (int)xw[g * LL];
        sel_g = cur_pend;
    }

#pragma unroll 1
    for (int step = 1; step < LL; step++) {
        // deferred head of the previous step
        logp = head_update(pend, cur_pend, bo0, bo1, logp);

        ull accg = 0ull;
        u32 nA0[4], nA1[4];
        nA0[1] = 0u; nA0[3] = 0u; nA1[1] = 0u; nA1[3] = 0u;

#pragma unroll
        for (int m = 0; m < 4; m++) {
            // gate chains: C = init(sel); depth-2 MMA per gate
            u32 ci0 = sel_g ? ini1[m]      : ini0[m];
            u32 cf0 = sel_g ? ini1[m + 4]  : ini0[m + 4];
            u32 cg0 = sel_g ? ini1[m + 8]  : ini0[m + 8];
            u32 co0 = sel_g ? ini1[m + 12] : ini0[m + 12];

            u32 di0, di1, df0, df1, dg0, dg1, do0, do1;
            mma_f16(di0, di1, A0[0],A0[1],A0[2],A0[3], bf[m][0][0],    bf[m][0][1],    ci0, 0u);
            mma_f16(di0, di1, A1[0],A1[1],A1[2],A1[3], bf[m][1][0],    bf[m][1][1],    di0, di1);
            mma_f16(df0, df1, A0[0],A0[1],A0[2],A0[3], bf[m+4][0][0],  bf[m+4][0][1],  cf0, 0u);
            mma_f16(df0, df1, A1[0],A1[1],A1[2],A1[3], bf[m+4][1][0],  bf[m+4][1][1],  df0, df1);
            mma_f16(dg0, dg1, A0[0],A0[1],A0[2],A0[3], bf[m+8][0][0],  bf[m+8][0][1],  cg0, 0u);
            mma_f16(dg0, dg1, A1[0],A1[1],A1[2],A1[3], bf[m+8][1][0],  bf[m+8][1][1],  dg0, dg1);
            mma_f16(do0, do1, A0[0],A0[1],A0[2],A0[3], bf[m+12][0][0], bf[m+12][0][1], co0, 0u);
            mma_f16(do0, do1, A1[0],A1[1],A1[2],A1[3], bf[m+12][1][0], bf[m+12][1][1], do0, do1);
            (void)di1; (void)df1; (void)dg1; (void)do1;

            // d0 = packed (u0,u1) gate pair for row g -> tail directly
            u32 pg = lstm_tail(di0, df0, dg0, do0, cst[m], h05);
            if (m == 0)      nA0[0] = pg;
            else if (m == 1) nA0[2] = pg;
            else if (m == 2) nA1[0] = pg;
            else             nA1[2] = pg;

            __half2 h2 = bits_h2(pg);
            float h0 = __low2float(h2), h1 = __high2float(h2);
            accg = fma2(pack2(h0, h0), wo[2 * m],     accg);
            accg = fma2(pack2(h1, h1), wo[2 * m + 1], accg);
        }

        // stage this step's head; advance sel
        pend = accg;
        int cur = (int)xw[g * LL + step];
        cur_pend = cur;
        sel_g = cur;
#pragma unroll
        for (int i = 0; i < 4; i++) { A0[i] = nA0[i]; A1[i] = nA1[i]; }
    }

    // flush the last step's head
    logp = head_update(pend, cur_pend, bo0, bo1, logp);

    if (t == 0)
        out[base_b + g] = 0.5f * logp;
}

extern "C" void kernel_launch(void* const* d_in, const int* in_sizes, int n_in,
                              void* d_out, int out_size) {
    const int* x = (const int*)d_in[0];
    const float* Wi = (const float*)d_in[1];
    const float* Wh = (const float*)d_in[2];
    const float* bh = (const float*)d_in[3];
    const float* Wo = (const float*)d_in[4];
    const float* bo = (const float*)d_in[5];
    float* out = (float*)d_out;

    const int batch = in_sizes[0] / LL;              // 4096
    const int blocks = batch / ROWS_PER_BLOCK;       // 128 blocks x 4 warps

    lstm_kernel<<<blocks, THREADS_PER_BLOCK>>>(x, Wi, Wh, bh, Wo, bo, out);
}